// round 8
// baseline (speedup 1.0000x reference)
#include <cuda_runtime.h>
#include <cuda_bf16.h>

#define Bc 8
#define Nmax 34000
#define Mc 64
#define EPSL 1e-7f
#define FULLM 0xFFFFFFFFu
#define DCHUNK 1024     // anchors per fused decode+filter block (256 thr * 4)
#define NCH 128         // reduce chunks per batch

// Scratch (static device globals; zero-initialized at load; no allocation allowed)
__device__ float4       g_pb[Bc * Nmax];
__device__ float        g_at1[Bc * Nmax];
__device__ unsigned int g_it[Bc * Nmax];
__device__ float        g_part2[Bc * NCH * 3];
__device__ unsigned int g_cnt;                            // zeroed by k_reduce epilogue
__device__ unsigned int g_cnt_m[Bc * Mc];                 // zeroed by k_reduce epilogue
__device__ unsigned int g_list[(size_t)Bc * Mc * Nmax];   // survivor anchor indices

// ---------------------------------------------------------------------------
// Scalar DFL decode of one anchor (column n of a [64, N] slab).
// ---------------------------------------------------------------------------
__device__ __forceinline__ float4 decode_one(const float* __restrict__ base, int N) {
    float pb[4];
#pragma unroll
    for (int k = 0; k < 4; k++) {
        float s = 0.f, e = 0.f;
#pragma unroll
        for (int r = 0; r < 16; r++) {
            float t = __expf(base[(size_t)(k * 16 + r) * N]);
            s += t; e += t * (float)r;
        }
        pb[k] = __fdividef(e, s);
    }
    return make_float4(pb[0], pb[1], pb[2], pb[3]);
}

// ---------------------------------------------------------------------------
// Fused kernel: DFL decode (4 anchors/thread) + overlap filter.
// Grid (ceil(N/DCHUNK), B), 256 threads.
//   decode -> g_pb, g_at1, zero g_it
//   filter -> append anchors with inter(target m) > 0 to per-(b,m) lists.
// Count-then-write: smem counters (no atomic-return dependency in the hot
// loop), one concurrent batch of 64 global atomicAdds per block, then smem
// cursors for slot assignment. Only pairs with inter>0 can have ciou>0.
// ---------------------------------------------------------------------------
__global__ __launch_bounds__(256) void k_decfil(const float* __restrict__ boxes,
                                                const float* __restrict__ targets,
                                                int N, int aligned) {
    const int b   = blockIdx.y;
    const int c0  = blockIdx.x * DCHUNK;
    const int tid = threadIdx.x;

    __shared__ float4 s_t[Mc];
    __shared__ int    s_cnt[Mc];
    __shared__ int    s_base[Mc];

    if (tid < Mc) {
        const float* t = targets + ((size_t)b * Mc + tid) * 4;
        s_t[tid] = make_float4(t[0], t[1], t[2], t[3]);
        s_cnt[tid] = 0;
    }
    __syncthreads();

    const int n0 = c0 + tid * 4;
    float4 pbox[4];
    bool   val[4];
#pragma unroll
    for (int j = 0; j < 4; j++) val[j] = false;

    if (n0 < N) {
        const float* base = boxes + (size_t)b * 64 * N + n0;
        size_t o = (size_t)b * N + n0;
        if (aligned && n0 + 4 <= N) {
            // vector path: float4 across 4 consecutive anchors
            float out[4][4];
#pragma unroll
            for (int k = 0; k < 4; k++) {
                float s0=0.f,s1=0.f,s2=0.f,s3=0.f, e0=0.f,e1=0.f,e2=0.f,e3=0.f;
#pragma unroll
                for (int r = 0; r < 16; r++) {
                    float4 x = *(const float4*)(base + (size_t)(k * 16 + r) * N);
                    float fr = (float)r;
                    float t0 = __expf(x.x), t1 = __expf(x.y), t2 = __expf(x.z), t3 = __expf(x.w);
                    s0 += t0; s1 += t1; s2 += t2; s3 += t3;
                    e0 += t0 * fr; e1 += t1 * fr; e2 += t2 * fr; e3 += t3 * fr;
                }
                out[k][0] = __fdividef(e0, s0);
                out[k][1] = __fdividef(e1, s1);
                out[k][2] = __fdividef(e2, s2);
                out[k][3] = __fdividef(e3, s3);
            }
#pragma unroll
            for (int j = 0; j < 4; j++)
                pbox[j] = make_float4(out[0][j], out[1][j], out[2][j], out[3][j]);
#pragma unroll
            for (int j = 0; j < 4; j++) {
                g_pb[o + j]  = pbox[j];
                g_at1[o + j] = atanf(__fdividef(pbox[j].z - pbox[j].x,
                                                pbox[j].w - pbox[j].y + EPSL));
                val[j] = (pbox[j].z > pbox[j].x) && (pbox[j].w > pbox[j].y);
            }
            *(uint4*)&g_it[o] = make_uint4(0u, 0u, 0u, 0u);
        } else {
            // scalar tail / unaligned path
#pragma unroll
            for (int j = 0; j < 4; j++) {
                if (n0 + j < N) {
                    pbox[j] = decode_one(base + j, N);
                    g_pb[o + j]  = pbox[j];
                    g_at1[o + j] = atanf(__fdividef(pbox[j].z - pbox[j].x,
                                                    pbox[j].w - pbox[j].y + EPSL));
                    g_it[o + j] = 0u;
                    val[j] = (pbox[j].z > pbox[j].x) && (pbox[j].w > pbox[j].y);
                }
            }
        }
    }
    __syncthreads();

    const int moff = (tid >> 5) * 8;   // stagger m order per warp (de-burst counters)

    // Pass A: count hits per target (fire-and-forget smem atomics)
    for (int mm = 0; mm < Mc; mm++) {
        int m = (mm + moff) & (Mc - 1);
        float4 t = s_t[m];
        int h = 0;
#pragma unroll
        for (int j = 0; j < 4; j++) {
            float iw = fminf(pbox[j].z, t.z) - fmaxf(pbox[j].x, t.x);
            float ih = fminf(pbox[j].w, t.w) - fmaxf(pbox[j].y, t.y);
            if (val[j] && iw > 0.f && ih > 0.f) h++;
        }
        if (h) atomicAdd(&s_cnt[m], h);
    }
    __syncthreads();

    // One concurrent batch of global reservations (64 parallel ATOMGs)
    if (tid < Mc) {
        int c = s_cnt[tid];
        s_base[tid] = c ? (int)atomicAdd(&g_cnt_m[b * Mc + tid], (unsigned)c) : 0;
        s_cnt[tid] = 0;   // reuse as write cursor
    }
    __syncthreads();

    // Pass B: assign slots via smem cursors, write indices
    for (int mm = 0; mm < Mc; mm++) {
        int m = (mm + moff) & (Mc - 1);
        float4 t = s_t[m];
        int h = 0, hm = 0;
#pragma unroll
        for (int j = 0; j < 4; j++) {
            float iw = fminf(pbox[j].z, t.z) - fmaxf(pbox[j].x, t.x);
            float ih = fminf(pbox[j].w, t.w) - fmaxf(pbox[j].y, t.y);
            if (val[j] && iw > 0.f && ih > 0.f) { h++; hm |= (1 << j); }
        }
        if (h) {
            int slot = atomicAdd(&s_cnt[m], h);
            unsigned* dst = &g_list[(size_t)(b * Mc + m) * Nmax + s_base[m] + slot];
            int k = 0;
#pragma unroll
            for (int j = 0; j < 4; j++)
                if (hm & (1 << j)) dst[k++] = (unsigned)(n0 + j);
        }
    }
}

// ---------------------------------------------------------------------------
// Kernel 2: per-(b,m) exact top-10 ciou over the survivor list, scatter
// positive values via atomicMax on float bits (order-preserving, commutative).
// ---------------------------------------------------------------------------
__global__ __launch_bounds__(256) void k_ciou(const float* __restrict__ targets, int N) {
    const int m = blockIdx.x;
    const int b = blockIdx.y;
    const int bm = b * Mc + m;
    const int tid  = threadIdx.x;
    const int lane = tid & 31;
    const int wid  = tid >> 5;

    const float* t = targets + (size_t)bm * 4;
    const float x21 = t[0], y21 = t[1], x22 = t[2], y22 = t[3];
    const float w2 = x22 - x21, h2 = y22 - y21;
    const float area2 = w2 * h2;
    const float at2 = atanf(__fdividef(w2, h2 + EPSL));
    const float sx = x21 + x22, sy = y21 + y22;
    const float VP = 4.0f / (float)(M_PI * M_PI);

    unsigned cnt = g_cnt_m[bm];
    if (cnt > (unsigned)N) cnt = (unsigned)N;

    unsigned long long top[10];
#pragma unroll
    for (int j = 0; j < 10; j++) top[j] = 0ull;

    const float4* __restrict__ pb = g_pb + (size_t)b * N;
    const float*  __restrict__ a1 = g_at1 + (size_t)b * N;
    const unsigned* __restrict__ lst = g_list + (size_t)bm * Nmax;

    for (unsigned i = tid; i < cnt; i += 256) {
        unsigned n = lst[i];
        float4 p = pb[n];
        float at1 = a1[n];
        float w1 = p.z - p.x, h1 = p.w - p.y;

        float iw = fminf(p.z, x22) - fmaxf(p.x, x21); iw = fmaxf(iw, 0.f);
        float ih = fminf(p.w, y22) - fmaxf(p.y, y21); ih = fmaxf(ih, 0.f);
        float inter = iw * ih;
        float uni = w1 * h1 + area2 - inter + EPSL;
        float iou = __fdividef(inter, uni);

        float cw = fmaxf(p.z, x22) - fminf(p.x, x21);
        float ch = fmaxf(p.w, y22) - fminf(p.y, y21);
        float c2 = cw * cw + ch * ch + EPSL;

        float dx = sx - p.x - p.z;
        float dy = sy - p.y - p.w;
        float rho2 = (dx * dx + dy * dy) * 0.25f;

        float d = at2 - at1;
        float v = VP * d * d;
        float av = __fdividef(v * v, v - iou + 1.0f + EPSL);
        float ciou = iou - __fdividef(rho2, c2) - av;

        unsigned u = __float_as_uint(ciou);
        unsigned key = (u & 0x80000000u) ? ~u : (u | 0x80000000u);
        unsigned long long pk =
            ((unsigned long long)key << 32) | (unsigned long long)(0xFFFFFFFFu - n);

        if (pk > top[9]) {
#pragma unroll
            for (int j = 0; j < 10; j++) {
                if (pk > top[j]) { unsigned long long tmp = top[j]; top[j] = pk; pk = tmp; }
            }
        }
    }

    __shared__ unsigned long long cand[2560];
    __shared__ unsigned long long wval[8];
    __shared__ int                wpos[8];
    __shared__ unsigned long long s_best;
    __shared__ int                s_bpos;

#pragma unroll
    for (int j = 0; j < 10; j++) cand[tid * 10 + j] = top[j];
    __syncthreads();

    for (int round = 0; round < 10; ++round) {
        unsigned long long mx = 0ull; int mp = tid * 10;
#pragma unroll
        for (int j = 0; j < 10; j++) {
            unsigned long long c = cand[tid * 10 + j];
            if (c > mx) { mx = c; mp = tid * 10 + j; }
        }
#pragma unroll
        for (int off = 16; off > 0; off >>= 1) {
            unsigned long long ov = __shfl_down_sync(FULLM, mx, off);
            int op = __shfl_down_sync(FULLM, mp, off);
            if (ov > mx) { mx = ov; mp = op; }
        }
        if (lane == 0) { wval[wid] = mx; wpos[wid] = mp; }
        __syncthreads();
        if (wid == 0) {
            unsigned long long v2 = (lane < 8) ? wval[lane] : 0ull;
            int p2 = (lane < 8) ? wpos[lane] : 0;
#pragma unroll
            for (int off = 4; off > 0; off >>= 1) {
                unsigned long long ov = __shfl_down_sync(FULLM, v2, off);
                int op = __shfl_down_sync(FULLM, p2, off);
                if (ov > v2) { v2 = ov; p2 = op; }
            }
            if (lane == 0) { s_best = v2; s_bpos = p2; }
        }
        __syncthreads();
        unsigned long long best = s_best;
        int bp = s_bpos;
        unsigned key = (unsigned)(best >> 32);
        if (key <= 0x80000000u) break;   // value <= 0: nothing left to scatter

        if (tid == 0) {
            unsigned n = 0xFFFFFFFFu - (unsigned)(best & 0xFFFFFFFFull);
            atomicMax(&g_it[(size_t)b * N + n], key ^ 0x80000000u);
        }
        if (tid == bp / 10) cand[bp] = 0ull;
        __syncthreads();
    }
}

// ---------------------------------------------------------------------------
// Kernel 3: parallel per-slice reductions, grid (NCH, B). Last block does the
// deterministic fixed-order final combine and re-zeroes counters for the
// next graph replay.
// ---------------------------------------------------------------------------
__global__ __launch_bounds__(256) void k_reduce(const float* __restrict__ scores, int N,
                                                float* out, int out_size) {
    const int c = blockIdx.x;
    const int b = blockIdx.y;
    const int tid = threadIdx.x;
    const int L = (N + NCH - 1) / NCH;
    const int n0 = c * L;
    const int n1 = min(n0 + L, N);

    float np = 0.f, bs = 0.f, bc = 0.f;
    const unsigned int* __restrict__ it = g_it + (size_t)b * N;
    const float* __restrict__ sc = scores + (size_t)b * N;
    for (int n = n0 + tid; n < n1; n += 256) {
        float iv = __uint_as_float(it[n]);
        float s = sc[n];
        if (iv > 0.f) { np += 1.f; bs += 1.f - iv; }
        bc += fmaxf(s, 0.f) - s * iv + __logf(1.f + __expf(-fabsf(s)));
    }
    __shared__ float r0[256], r1[256], r2[256];
    __shared__ int s_last;
    r0[tid] = np; r1[tid] = bs; r2[tid] = bc;
    __syncthreads();
    for (int s = 128; s > 0; s >>= 1) {
        if (tid < s) { r0[tid] += r0[tid + s]; r1[tid] += r1[tid + s]; r2[tid] += r2[tid + s]; }
        __syncthreads();
    }
    if (tid == 0) {
        int slot = b * NCH + c;
        g_part2[slot * 3 + 0] = r0[0];
        g_part2[slot * 3 + 1] = r1[0];
        g_part2[slot * 3 + 2] = r2[0];
        __threadfence();
        unsigned int done = atomicAdd(&g_cnt, 1u);
        s_last = (done == (unsigned)(NCH * Bc - 1)) ? 1 : 0;
    }
    __syncthreads();
    if (!s_last) return;

    // Final combine (deterministic fixed order) in the last block.
    __shared__ float f0[Bc * NCH], f1[Bc * NCH], f2[Bc * NCH];
    __shared__ float bx[Bc], ob[Bc];
    for (int i = tid; i < Bc * NCH; i += 256) {
        f0[i] = g_part2[i * 3 + 0];
        f1[i] = g_part2[i * 3 + 1];
        f2[i] = g_part2[i * 3 + 2];
    }
    __syncthreads();
    if (tid < Bc) {
        float nps = 0.f, bss = 0.f, bcs = 0.f;
        for (int cc = 0; cc < NCH; cc++) {
            nps += f0[tid * NCH + cc];
            bss += f1[tid * NCH + cc];
            bcs += f2[tid * NCH + cc];
        }
        bx[tid] = (nps > 0.f) ? __fdividef(bss, fmaxf(nps, 1.f)) : 0.f;
        ob[tid] = bcs / (float)N;
    }
    __syncthreads();
    if (tid == 0) {
        float box = 0.f, obj = 0.f;
        for (int bb = 0; bb < Bc; bb++) { box += bx[bb]; obj += ob[bb]; }
        float total = (7.5f * box + 1.0f * obj) / (float)Bc;
        out[0] = total;
        if (out_size > 1) out[1] = box;
        if (out_size > 2) out[2] = obj;
    }
    // Reset counters for the next replay (first call relies on static zero-init).
    for (int i = tid; i < Bc * Mc; i += 256) g_cnt_m[i] = 0u;
    if (tid == 0) g_cnt = 0u;
}

extern "C" void kernel_launch(void* const* d_in, const int* in_sizes, int n_in,
                              void* d_out, int out_size) {
    const float* boxes   = (const float*)d_in[0];   // [8, 64, N]
    const float* scores  = (const float*)d_in[1];   // [8, N]
    const float* targets = (const float*)d_in[2];   // [8, 64, 4]
    int N = in_sizes[1] / Bc;
    if (N > Nmax) N = Nmax;
    int aligned = ((N & 3) == 0) ? 1 : 0;

    dim3 gd((N + DCHUNK - 1) / DCHUNK, Bc);
    k_decfil<<<gd, 256>>>(boxes, targets, N, aligned);
    dim3 gc(Mc, Bc);
    k_ciou<<<gc, 256>>>(targets, N);
    dim3 gr(NCH, Bc);
    k_reduce<<<gr, 256>>>(scores, N, (float*)d_out, out_size);
}